// round 14
// baseline (speedup 1.0000x reference)
#include <cuda_runtime.h>
#include <cuda_fp16.h>
#include <math.h>
#include <stdint.h>

#define NDIM 4096
#define DDIM 1024
#define HSZ ((size_t)NDIM * DDIM)
#define NN  ((size_t)NDIM * NDIM)
#define MBZ ((size_t)NDIM * 128)   // uint32 words per bit-mask matrix

// ---------------- scratch (device globals) ----------------
__device__ __half g_Sh[3 * NN];                    // fp16 scores -> probs (in place)
__device__ __half g_Hh[3 * HSZ];                   // fp16(H / H_low / H_high)
__device__ __half g_HT[3 * HSZ];                   // fp16 transposed KV
__device__ __half g_H4[(size_t)NDIM * 3 * DDIM];   // fp16 concat AV outputs
__device__ __half g_Wh[(size_t)DDIM * 3 * DDIM];   // fp16(W)
__device__ uint32_t g_Mb[3 * MBZ];                 // bit masks: z0=L, z1=(B_low!=0)^T, z2=B_high

// ---------------- PTX helpers (portable tier) ----------------
__device__ __forceinline__ uint32_t smem_u32(const void* p) {
    uint32_t a;
    asm("{ .reg .u64 t; cvta.to.shared.u64 t, %1; cvt.u32.u64 %0, t; }" : "=r"(a) : "l"(p));
    return a;
}
__device__ __forceinline__ void cp_async16(uint32_t dst, const void* src) {
    asm volatile("cp.async.cg.shared.global [%0], [%1], 16;" :: "r"(dst), "l"(src) : "memory");
}
__device__ __forceinline__ void cp_commit() {
    asm volatile("cp.async.commit_group;" ::: "memory");
}
template <int N>
__device__ __forceinline__ void cp_wait() {
    asm volatile("cp.async.wait_group %0;" :: "n"(N) : "memory");
}
__device__ __forceinline__ void ldsm4(uint32_t* d, uint32_t addr) {
    asm volatile("ldmatrix.sync.aligned.m8n8.x4.shared.b16 {%0,%1,%2,%3}, [%4];"
        : "=r"(d[0]), "=r"(d[1]), "=r"(d[2]), "=r"(d[3]) : "r"(addr));
}
__device__ __forceinline__ void mma_f32(float* c, const uint32_t* a, const uint32_t* b) {
    asm volatile("mma.sync.aligned.m16n8k16.row.col.f32.f16.f16.f32 "
        "{%0,%1,%2,%3}, {%4,%5,%6,%7}, {%8,%9}, {%0,%1,%2,%3};"
        : "+f"(c[0]), "+f"(c[1]), "+f"(c[2]), "+f"(c[3])
        : "r"(a[0]), "r"(a[1]), "r"(a[2]), "r"(a[3]), "r"(b[0]), "r"(b[1]));
}
__device__ __forceinline__ void mma_f16acc(uint32_t* c, const uint32_t* a, const uint32_t* b) {
    asm volatile("mma.sync.aligned.m16n8k16.row.col.f16.f16.f16.f16 "
        "{%0,%1}, {%2,%3,%4,%5}, {%6,%7}, {%0,%1};"
        : "+r"(c[0]), "+r"(c[1])
        : "r"(a[0]), "r"(a[1]), "r"(a[2]), "r"(a[3]), "r"(b[0]), "r"(b[1]));
}

// SMEM tile: 128 rows x 32 fp16 (64B/row), four 16B chunks/row, XOR swizzle.
__device__ __forceinline__ uint32_t soff64(int r, int c) {
    return (uint32_t)(r * 64 + ((c ^ ((r >> 1) & 3)) << 4));
}

#define OPB (128 * 64)
#define STB (2 * OPB)
#define NST 3
#define BKE 32

// ============================================================================
// HMMA NT GEMM. ACC16: f16 accum (scores). !ACC16: f32 accum.
// 3 CTAs/SM via launch bounds (regs capped at 85 -> 24 warps/SM).
// mode 0: Ch = fp16(alpha * acc)   mode 1 (!ACC16): Cf = tanh(acc + bias[n])
// ============================================================================
template <bool ACC16>
__global__ void __launch_bounds__(256, 3) gemm_tcore(
    const __half* __restrict__ A, size_t sAz, int lda,
    const __half* __restrict__ B, size_t sBz, int ldb,
    int K, int mode, float alpha,
    __half* __restrict__ Ch, float* __restrict__ Cf, size_t sCz, int ldc,
    const float* __restrict__ bias)
{
    __shared__ __align__(128) char sm[NST * STB];

    const int t    = threadIdx.x;
    const int lane = t & 31;
    const int wid  = t >> 5;
    const int wm   = (wid & 3) * 32;
    const int wn   = (wid >> 2) * 64;
    const int m0   = blockIdx.y * 128;
    const int n0   = blockIdx.x * 128;
    const int z    = blockIdx.z;
    A += (size_t)z * sAz;
    B += (size_t)z * sBz;
    const uint32_t sbase = smem_u32(sm);

    const int rl = t >> 2;
    const int cl = t & 3;
    const uint32_t st0 = soff64(rl, cl);
    const uint32_t st1 = soff64(rl + 64, cl);
    const __half* gA0 = A + (size_t)(m0 + rl) * lda + cl * 8;
    const __half* gA1 = A + (size_t)(m0 + rl + 64) * lda + cl * 8;
    const __half* gB0 = B + (size_t)(n0 + rl) * ldb + cl * 8;
    const __half* gB1 = B + (size_t)(n0 + rl + 64) * ldb + cl * 8;

    uint32_t adA[2][2], adB[2][4];
    {
        const int mm = lane >> 3;
#pragma unroll
        for (int ks = 0; ks < 2; ks++) {
#pragma unroll
            for (int i = 0; i < 2; i++)
                adA[ks][i] = soff64(wm + i * 16 + (mm & 1) * 8 + (lane & 7),
                                    2 * ks + (mm >> 1));
#pragma unroll
            for (int j = 0; j < 4; j++)
                adB[ks][j] = soff64(wn + j * 16 + (mm >> 1) * 8 + (lane & 7),
                                    2 * ks + (mm & 1));
        }
    }

    float    accf[2][8][4];
    uint32_t acch[2][8][2];
#pragma unroll
    for (int i = 0; i < 2; i++)
#pragma unroll
        for (int j = 0; j < 8; j++) {
            if (ACC16) { acch[i][j][0] = 0u; acch[i][j][1] = 0u; }
            else {
#pragma unroll
                for (int q = 0; q < 4; q++) accf[i][j][q] = 0.f;
            }
        }

    const int T = K / BKE;

#pragma unroll
    for (int s = 0; s < NST - 1; s++) {
        const uint32_t d = sbase + s * STB;
        const int k = s * BKE;
        cp_async16(d + st0,       gA0 + k);
        cp_async16(d + st1,       gA1 + k);
        cp_async16(d + OPB + st0, gB0 + k);
        cp_async16(d + OPB + st1, gB1 + k);
        cp_commit();
    }

    for (int tt = 0; tt < T; tt++) {
        __syncthreads();
        const int nt = tt + NST - 1;
        if (nt < T) {
            const uint32_t d = sbase + (nt % NST) * STB;
            const int k = nt * BKE;
            cp_async16(d + st0,       gA0 + k);
            cp_async16(d + st1,       gA1 + k);
            cp_async16(d + OPB + st0, gB0 + k);
            cp_async16(d + OPB + st1, gB1 + k);
        }
        cp_commit();
        cp_wait<NST - 2>();
        __syncthreads();

        const uint32_t sb = sbase + (tt % NST) * STB;
#pragma unroll
        for (int ks = 0; ks < 2; ks++) {
            uint32_t a[2][4], b[8][2];
            ldsm4(a[0], sb + adA[ks][0]);
            ldsm4(a[1], sb + adA[ks][1]);
#pragma unroll
            for (int j = 0; j < 4; j++) {
                uint32_t tmp[4];
                ldsm4(tmp, sb + OPB + adB[ks][j]);
                b[2*j][0]   = tmp[0]; b[2*j][1]   = tmp[1];
                b[2*j+1][0] = tmp[2]; b[2*j+1][1] = tmp[3];
            }
#pragma unroll
            for (int i = 0; i < 2; i++)
#pragma unroll
                for (int j = 0; j < 8; j++) {
                    if (ACC16) mma_f16acc(acch[i][j], a[i], b[j]);
                    else       mma_f32  (accf[i][j], a[i], b[j]);
                }
        }
    }

    const int row0 = m0 + wm + (lane >> 2);
    const int colb = n0 + wn + (lane & 3) * 2;
    if (ACC16) {
        __half* Cz = Ch + (size_t)z * sCz;
        const __half2 sc2 = __float2half2_rn(alpha);
#pragma unroll
        for (int i = 0; i < 2; i++) {
#pragma unroll
            for (int j = 0; j < 8; j++) {
                const int r0 = row0 + i * 16;
                const int col = colb + j * 8;
                *(__half2*)(Cz + (size_t)r0 * ldc + col)       = __hmul2(*(__half2*)&acch[i][j][0], sc2);
                *(__half2*)(Cz + (size_t)(r0 + 8) * ldc + col) = __hmul2(*(__half2*)&acch[i][j][1], sc2);
            }
        }
    } else if (mode == 0) {
        __half* Cz = Ch + (size_t)z * sCz;
#pragma unroll
        for (int i = 0; i < 2; i++) {
#pragma unroll
            for (int j = 0; j < 8; j++) {
                const int r0 = row0 + i * 16;
                const int col = colb + j * 8;
                const float* c = accf[i][j];
                __half2 v0; v0.x = __float2half_rn(c[0]); v0.y = __float2half_rn(c[1]);
                __half2 v1; v1.x = __float2half_rn(c[2]); v1.y = __float2half_rn(c[3]);
                *(__half2*)(Cz + (size_t)r0 * ldc + col)       = v0;
                *(__half2*)(Cz + (size_t)(r0 + 8) * ldc + col) = v1;
            }
        }
    } else {
#pragma unroll
        for (int i = 0; i < 2; i++) {
#pragma unroll
            for (int j = 0; j < 8; j++) {
                const int r0 = row0 + i * 16;
                const int col = colb + j * 8;
                const float* c = accf[i][j];
                *(float2*)(Cf + (size_t)r0 * ldc + col) =
                    make_float2(tanhf(c[0] + bias[col]), tanhf(c[1] + bias[col + 1]));
                *(float2*)(Cf + (size_t)(r0 + 8) * ldc + col) =
                    make_float2(tanhf(c[2] + bias[col]), tanhf(c[3] + bias[col + 1]));
            }
        }
    }
}

// ---------------- prep kernels ----------------
__global__ void roundH_kernel(const float* __restrict__ X0,
                              const float* __restrict__ X1,
                              const float* __restrict__ X2,
                              __half* __restrict__ Y, int per)
{
    const int zz = blockIdx.y;
    const float* X = (zz == 0) ? X0 : (zz == 1) ? X1 : X2;
    __half* Yz = Y + (size_t)zz * per;
    int i = (blockIdx.x * blockDim.x + threadIdx.x) * 4;
    if (i >= per) return;
    float4 v = *(const float4*)(X + i);
    __half2 a; a.x = __float2half_rn(v.x); a.y = __float2half_rn(v.y);
    __half2 b; b.x = __float2half_rn(v.z); b.y = __float2half_rn(v.w);
    *(__half2*)(Yz + i)     = a;
    *(__half2*)(Yz + i + 2) = b;
}

__global__ void round_kernel(const float* __restrict__ X,
                             __half* __restrict__ hi, int count)
{
    int i = (blockIdx.x * blockDim.x + threadIdx.x) * 4;
    if (i >= count) return;
    float4 v = *(const float4*)(X + i);
    __half2 a; a.x = __float2half_rn(v.x); a.y = __float2half_rn(v.y);
    __half2 b; b.x = __float2half_rn(v.z); b.y = __float2half_rn(v.w);
    *(__half2*)(hi + i)     = a;
    *(__half2*)(hi + i + 2) = b;
}

__global__ void round_t3_kernel(const float* __restrict__ X0,
                                const float* __restrict__ X1,
                                const float* __restrict__ X2,
                                __half* __restrict__ hT, int R, int C)
{
    __shared__ float tile[32][33];
    const int zz = blockIdx.z;
    const float* X = (zz == 0) ? X0 : (zz == 1) ? X1 : X2;
    __half* o = hT + (size_t)zz * R * C;
    const int c0 = blockIdx.x * 32;
    const int r0 = blockIdx.y * 32;
    const int tx = threadIdx.x;
    const int ty = threadIdx.y;
#pragma unroll
    for (int j = ty; j < 32; j += 8)
        tile[j][tx] = X[(size_t)(r0 + j) * C + c0 + tx];
    __syncthreads();
#pragma unroll
    for (int j = ty; j < 32; j += 8)
        o[(size_t)(c0 + j) * R + r0 + tx] = __float2half_rn(tile[tx][j]);
}

// row-major bit-pack of (X != 0): one warp per row. grid (rows/8, 2)
__global__ void bitpack_rows_kernel(const float* __restrict__ L,
                                    const float* __restrict__ Bh,
                                    uint32_t* __restrict__ Mb)
{
    const int z = blockIdx.y;                    // 0 -> L (slot 0), 1 -> B_high (slot 2)
    const float* X = z ? Bh : L;
    uint32_t* outb = Mb + (z ? 2 * MBZ : 0);
    const int row  = blockIdx.x * 8 + (threadIdx.x >> 5);
    const int lane = threadIdx.x & 31;
    const float* rp = X + (size_t)row * NDIM;
    uint32_t* op = outb + (size_t)row * 128;
#pragma unroll 4
    for (int w = 0; w < 128; w++) {
        const float v = rp[w * 32 + lane];
        const unsigned b = __ballot_sync(0xffffffffu, v != 0.f);
        if (lane == 0) op[w] = b;
    }
}

// transposed bit-pack: out[r] bit c = (B[c][r] != 0). grid (128,128), block (32,8)
__global__ void bitpack_T_kernel(const float* __restrict__ B,
                                 uint32_t* __restrict__ outb)
{
    __shared__ unsigned char tile[32][33];
    const int bx = blockIdx.x * 32;   // input cols = output rows
    const int by = blockIdx.y * 32;   // input rows = output bit positions
    const int tx = threadIdx.x;
    const int ty = threadIdx.y;
#pragma unroll
    for (int j = ty; j < 32; j += 8)
        tile[j][tx] = (B[(size_t)(by + j) * NDIM + bx + tx] != 0.f) ? 1 : 0;
    __syncthreads();
#pragma unroll
    for (int jj = 0; jj < 4; jj++) {
        const int ic = ty * 4 + jj;
        const unsigned bits = __ballot_sync(0xffffffffu, tile[tx][ic] != 0);
        if (tx == 0) outb[(size_t)(bx + ic) * 128 + (by >> 5)] = bits;
    }
}

// ============================================================================
// merged double softmax with bit mask; fp16 in/out (in place), grid (NDIM, 3)
// ============================================================================
__device__ __forceinline__ float warp_red_max(float v) {
#pragma unroll
    for (int o = 16; o; o >>= 1) v = fmaxf(v, __shfl_xor_sync(0xffffffffu, v, o));
    return v;
}
__device__ __forceinline__ float warp_red_sum(float v) {
#pragma unroll
    for (int o = 16; o; o >>= 1) v += __shfl_xor_sync(0xffffffffu, v, o);
    return v;
}
template <bool IS_MAX>
__device__ __forceinline__ float block_red(float v, float* red, int t) {
    v = IS_MAX ? warp_red_max(v) : warp_red_sum(v);
    __syncthreads();
    if ((t & 31) == 0) red[t >> 5] = v;
    __syncthreads();
    if (t < 32) {
        float x = (t < 8) ? red[t] : (IS_MAX ? -INFINITY : 0.f);
        x = IS_MAX ? warp_red_max(x) : warp_red_sum(x);
        if (t == 0) red[0] = x;
    }
    __syncthreads();
    return red[0];
}

__global__ void __launch_bounds__(256) softmax2_kernel(
    __half* __restrict__ Sbase, const uint32_t* __restrict__ Mb)
{
    __shared__ float red[32];
    const int t = threadIdx.x;
    const size_t row = blockIdx.x;
    const int z = blockIdx.y;
    __half* Srow = Sbase + (size_t)z * NN + row * NDIM;
    const uint32_t* mb = Mb + (size_t)z * MBZ + row * 128;

    float r[16];
    float mx = -INFINITY;
#pragma unroll
    for (int c = 0; c < 2; c++) {
        uint4 raw = *(const uint4*)(Srow + c * 2048 + t * 8);
        const __half2* h2 = (const __half2*)&raw;
#pragma unroll
        for (int q = 0; q < 4; q++) {
            float2 f = __half22float2(h2[q]);
            r[c*8 + 2*q]     = f.x;
            r[c*8 + 2*q + 1] = f.y;
            mx = fmaxf(mx, fmaxf(f.x, f.y));
        }
    }
    const float smax = block_red<true>(mx, red, t);

    float sum = 0.f;
#pragma unroll
    for (int i = 0; i < 16; i++) { r[i] = __expf(r[i] - smax); sum += r[i]; }
    const float inv = 1.f / block_red<false>(sum, red, t);

    float mx2 = -INFINITY;
#pragma unroll
    for (int c = 0; c < 2; c++) {
        const uint32_t w = __ldg(&mb[c * 64 + (t >> 2)]);
        const uint32_t bits = (w >> ((t & 3) * 8)) & 0xFFu;
#pragma unroll
        for (int i = 0; i < 8; i++) {
            r[c*8 + i] = ((bits >> i) & 1u) ? (r[c*8 + i] * inv) : 0.f;
            mx2 = fmaxf(mx2, r[c*8 + i]);
        }
    }
    const float smax2 = block_red<true>(mx2, red, t);

    float sum2 = 0.f;
#pragma unroll
    for (int i = 0; i < 16; i++) { r[i] = __expf(r[i] - smax2); sum2 += r[i]; }
    const float inv2 = 1.f / block_red<false>(sum2, red, t);

#pragma unroll
    for (int c = 0; c < 2; c++) {
        uint4 raw;
        __half2* h2 = (__half2*)&raw;
#pragma unroll
        for (int q = 0; q < 4; q++) {
            h2[q].x = __float2half_rn(r[c*8 + 2*q]     * inv2);
            h2[q].y = __float2half_rn(r[c*8 + 2*q + 1] * inv2);
        }
        *(uint4*)(Srow + c * 2048 + t * 8) = raw;
    }
}

// ============================================================================
// launch (R13 topology; only GEMM launch bounds changed)
// ============================================================================
extern "C" void kernel_launch(void* const* d_in, const int* in_sizes, int n_in,
                              void* d_out, int out_size)
{
    const float* L      = (const float*)d_in[0];
    const float* H      = (const float*)d_in[1];
    const float* B_low  = (const float*)d_in[2];
    const float* H_low  = (const float*)d_in[3];
    const float* B_high = (const float*)d_in[4];
    const float* H_high = (const float*)d_in[5];
    const float* W      = (const float*)d_in[6];
    const float* bvec   = (const float*)d_in[7];
    float* out = (float*)d_out;

    __half *Sh, *Hh, *HT, *H4, *Wh;
    uint32_t* Mb;
    cudaGetSymbolAddress((void**)&Sh, g_Sh);
    cudaGetSymbolAddress((void**)&Hh, g_Hh);
    cudaGetSymbolAddress((void**)&HT, g_HT);
    cudaGetSymbolAddress((void**)&H4, g_H4);
    cudaGetSymbolAddress((void**)&Wh, g_Wh);
    cudaGetSymbolAddress((void**)&Mb, g_Mb);

    const float scale = 0.03125f;  // 1/sqrt(1024)
    const int rt = 256;

    // [0] merged fp16 rounds of H tensors
    roundH_kernel<<<dim3((unsigned)(HSZ / 4 / rt), 3), rt>>>(H, H_low, H_high, Hh, (int)HSZ);
    // [1] bit masks for L and B_high (row-major)
    bitpack_rows_kernel<<<dim3(NDIM / 8, 2), 256>>>(L, B_high, Mb);
    // [2] transposed bit mask for B_low
    bitpack_T_kernel<<<dim3(NDIM / 32, NDIM / 32), dim3(32, 8)>>>(B_low, Mb + MBZ);

    // [3] merged score GEMM, f16 accumulators: S_z = scale * H @ Hh_z^T
    gemm_tcore<true><<<dim3(NDIM / 128, NDIM / 128, 3), 256>>>(
        Hh, 0, DDIM, Hh, HSZ, DDIM,
        DDIM, 0, scale, Sh, nullptr, NN, NDIM, nullptr);

    // [4] merged double softmax (in place, fp16, bit masks)
    softmax2_kernel<<<dim3(NDIM, 3), 256>>>(Sh, Mb);

    // [5] merged transposed fp16 KV copies
    round_t3_kernel<<<dim3(DDIM / 32, NDIM / 32, 3), dim3(32, 8)>>>(
        H, H_low, H_high, HT, NDIM, DDIM);

    // [6] merged AV GEMM, f32 accumulators
    gemm_tcore<false><<<dim3(DDIM / 128, NDIM / 128, 3), 256>>>(
        Sh, NN, NDIM, HT, HSZ, NDIM,
        NDIM, 0, 1.0f, H4, nullptr, DDIM, 3 * DDIM, nullptr);

    // [7] W fp16 round
    round_kernel<<<(int)((size_t)DDIM * 3 * DDIM / 4 / rt), rt>>>(
        W, Wh, (int)((size_t)DDIM * 3 * DDIM));

    // [8] output GEMM: out = tanh(H4 @ W^T + b)
    gemm_tcore<false><<<dim3(DDIM / 128, NDIM / 128, 1), 256>>>(
        H4, 0, 3 * DDIM, Wh, 0, 3 * DDIM,
        3 * DDIM, 1, 1.0f, nullptr, out, 0, DDIM, bvec);
}

// round 15
// speedup vs baseline: 1.3176x; 1.3176x over previous
#include <cuda_runtime.h>
#include <cuda_fp16.h>
#include <math.h>
#include <stdint.h>

#define NDIM 4096
#define DDIM 1024
#define HSZ ((size_t)NDIM * DDIM)
#define NN  ((size_t)NDIM * NDIM)
#define MBZ ((size_t)NDIM * 128)   // uint32 words per bit-mask matrix

// ---------------- scratch (device globals) ----------------
__device__ __half g_Sh[3 * NN];                    // fp16 scores -> probs (in place)
__device__ __half g_Hh[3 * HSZ];                   // fp16(H / H_low / H_high)
__device__ __half g_HT[3 * HSZ];                   // fp16 transposed KV
__device__ __half g_H4[(size_t)NDIM * 3 * DDIM];   // fp16 concat AV outputs
__device__ __half g_Wh[(size_t)DDIM * 3 * DDIM];   // fp16(W)
__device__ uint32_t g_Mb[3 * MBZ];                 // bit masks: z0=L, z1=(B_low!=0)^T, z2=B_high

// ---------------- PTX helpers (portable tier) ----------------
__device__ __forceinline__ uint32_t smem_u32(const void* p) {
    uint32_t a;
    asm("{ .reg .u64 t; cvta.to.shared.u64 t, %1; cvt.u32.u64 %0, t; }" : "=r"(a) : "l"(p));
    return a;
}
__device__ __forceinline__ void cp_async16(uint32_t dst, const void* src) {
    asm volatile("cp.async.cg.shared.global [%0], [%1], 16;" :: "r"(dst), "l"(src) : "memory");
}
__device__ __forceinline__ void cp_commit() {
    asm volatile("cp.async.commit_group;" ::: "memory");
}
template <int N>
__device__ __forceinline__ void cp_wait() {
    asm volatile("cp.async.wait_group %0;" :: "n"(N) : "memory");
}
__device__ __forceinline__ void ldsm4(uint32_t* d, uint32_t addr) {
    asm volatile("ldmatrix.sync.aligned.m8n8.x4.shared.b16 {%0,%1,%2,%3}, [%4];"
        : "=r"(d[0]), "=r"(d[1]), "=r"(d[2]), "=r"(d[3]) : "r"(addr));
}
__device__ __forceinline__ void mma_f32(float* c, const uint32_t* a, const uint32_t* b) {
    asm volatile("mma.sync.aligned.m16n8k16.row.col.f32.f16.f16.f32 "
        "{%0,%1,%2,%3}, {%4,%5,%6,%7}, {%8,%9}, {%0,%1,%2,%3};"
        : "+f"(c[0]), "+f"(c[1]), "+f"(c[2]), "+f"(c[3])
        : "r"(a[0]), "r"(a[1]), "r"(a[2]), "r"(a[3]), "r"(b[0]), "r"(b[1]));
}
__device__ __forceinline__ void mma_f16acc(uint32_t* c, const uint32_t* a, const uint32_t* b) {
    asm volatile("mma.sync.aligned.m16n8k16.row.col.f16.f16.f16.f16 "
        "{%0,%1}, {%2,%3,%4,%5}, {%6,%7}, {%0,%1};"
        : "+r"(c[0]), "+r"(c[1])
        : "r"(a[0]), "r"(a[1]), "r"(a[2]), "r"(a[3]), "r"(b[0]), "r"(b[1]));
}

// SMEM tile: 128 rows x 32 fp16 (64B/row), four 16B chunks/row, XOR swizzle.
__device__ __forceinline__ uint32_t soff64(int r, int c) {
    return (uint32_t)(r * 64 + ((c ^ ((r >> 1) & 3)) << 4));
}

#define OPB (128 * 64)
#define STB (2 * OPB)
#define NST 3
#define BKE 32

// ============================================================================
// HMMA NT GEMM. ACC16: f16 accum (scores), 3 CTAs/SM (verified 80 regs).
//              !ACC16: f32 accum, 2 CTAs/SM (verified 112 regs, no spills).
// mode 0: Ch = fp16(alpha * acc)   mode 1 (!ACC16): Cf = tanh(acc + bias[n])
// ============================================================================
template <bool ACC16>
__global__ void __launch_bounds__(256, ACC16 ? 3 : 2) gemm_tcore(
    const __half* __restrict__ A, size_t sAz, int lda,
    const __half* __restrict__ B, size_t sBz, int ldb,
    int K, int mode, float alpha,
    __half* __restrict__ Ch, float* __restrict__ Cf, size_t sCz, int ldc,
    const float* __restrict__ bias)
{
    __shared__ __align__(128) char sm[NST * STB];

    const int t    = threadIdx.x;
    const int lane = t & 31;
    const int wid  = t >> 5;
    const int wm   = (wid & 3) * 32;
    const int wn   = (wid >> 2) * 64;
    const int m0   = blockIdx.y * 128;
    const int n0   = blockIdx.x * 128;
    const int z    = blockIdx.z;
    A += (size_t)z * sAz;
    B += (size_t)z * sBz;
    const uint32_t sbase = smem_u32(sm);

    const int rl = t >> 2;
    const int cl = t & 3;
    const uint32_t st0 = soff64(rl, cl);
    const uint32_t st1 = soff64(rl + 64, cl);
    const __half* gA0 = A + (size_t)(m0 + rl) * lda + cl * 8;
    const __half* gA1 = A + (size_t)(m0 + rl + 64) * lda + cl * 8;
    const __half* gB0 = B + (size_t)(n0 + rl) * ldb + cl * 8;
    const __half* gB1 = B + (size_t)(n0 + rl + 64) * ldb + cl * 8;

    uint32_t adA[2][2], adB[2][4];
    {
        const int mm = lane >> 3;
#pragma unroll
        for (int ks = 0; ks < 2; ks++) {
#pragma unroll
            for (int i = 0; i < 2; i++)
                adA[ks][i] = soff64(wm + i * 16 + (mm & 1) * 8 + (lane & 7),
                                    2 * ks + (mm >> 1));
#pragma unroll
            for (int j = 0; j < 4; j++)
                adB[ks][j] = soff64(wn + j * 16 + (mm >> 1) * 8 + (lane & 7),
                                    2 * ks + (mm & 1));
        }
    }

    float    accf[2][8][4];
    uint32_t acch[2][8][2];
#pragma unroll
    for (int i = 0; i < 2; i++)
#pragma unroll
        for (int j = 0; j < 8; j++) {
            if (ACC16) { acch[i][j][0] = 0u; acch[i][j][1] = 0u; }
            else {
#pragma unroll
                for (int q = 0; q < 4; q++) accf[i][j][q] = 0.f;
            }
        }

    const int T = K / BKE;

#pragma unroll
    for (int s = 0; s < NST - 1; s++) {
        const uint32_t d = sbase + s * STB;
        const int k = s * BKE;
        cp_async16(d + st0,       gA0 + k);
        cp_async16(d + st1,       gA1 + k);
        cp_async16(d + OPB + st0, gB0 + k);
        cp_async16(d + OPB + st1, gB1 + k);
        cp_commit();
    }

    for (int tt = 0; tt < T; tt++) {
        __syncthreads();
        const int nt = tt + NST - 1;
        if (nt < T) {
            const uint32_t d = sbase + (nt % NST) * STB;
            const int k = nt * BKE;
            cp_async16(d + st0,       gA0 + k);
            cp_async16(d + st1,       gA1 + k);
            cp_async16(d + OPB + st0, gB0 + k);
            cp_async16(d + OPB + st1, gB1 + k);
        }
        cp_commit();
        cp_wait<NST - 2>();
        __syncthreads();

        const uint32_t sb = sbase + (tt % NST) * STB;
#pragma unroll
        for (int ks = 0; ks < 2; ks++) {
            uint32_t a[2][4], b[8][2];
            ldsm4(a[0], sb + adA[ks][0]);
            ldsm4(a[1], sb + adA[ks][1]);
#pragma unroll
            for (int j = 0; j < 4; j++) {
                uint32_t tmp[4];
                ldsm4(tmp, sb + OPB + adB[ks][j]);
                b[2*j][0]   = tmp[0]; b[2*j][1]   = tmp[1];
                b[2*j+1][0] = tmp[2]; b[2*j+1][1] = tmp[3];
            }
#pragma unroll
            for (int i = 0; i < 2; i++)
#pragma unroll
                for (int j = 0; j < 8; j++) {
                    if (ACC16) mma_f16acc(acch[i][j], a[i], b[j]);
                    else       mma_f32  (accf[i][j], a[i], b[j]);
                }
        }
    }

    const int row0 = m0 + wm + (lane >> 2);
    const int colb = n0 + wn + (lane & 3) * 2;
    if (ACC16) {
        __half* Cz = Ch + (size_t)z * sCz;
        const __half2 sc2 = __float2half2_rn(alpha);
#pragma unroll
        for (int i = 0; i < 2; i++) {
#pragma unroll
            for (int j = 0; j < 8; j++) {
                const int r0 = row0 + i * 16;
                const int col = colb + j * 8;
                *(__half2*)(Cz + (size_t)r0 * ldc + col)       = __hmul2(*(__half2*)&acch[i][j][0], sc2);
                *(__half2*)(Cz + (size_t)(r0 + 8) * ldc + col) = __hmul2(*(__half2*)&acch[i][j][1], sc2);
            }
        }
    } else if (mode == 0) {
        __half* Cz = Ch + (size_t)z * sCz;
#pragma unroll
        for (int i = 0; i < 2; i++) {
#pragma unroll
            for (int j = 0; j < 8; j++) {
                const int r0 = row0 + i * 16;
                const int col = colb + j * 8;
                const float* c = accf[i][j];
                __half2 v0; v0.x = __float2half_rn(c[0]); v0.y = __float2half_rn(c[1]);
                __half2 v1; v1.x = __float2half_rn(c[2]); v1.y = __float2half_rn(c[3]);
                *(__half2*)(Cz + (size_t)r0 * ldc + col)       = v0;
                *(__half2*)(Cz + (size_t)(r0 + 8) * ldc + col) = v1;
            }
        }
    } else {
#pragma unroll
        for (int i = 0; i < 2; i++) {
#pragma unroll
            for (int j = 0; j < 8; j++) {
                const int r0 = row0 + i * 16;
                const int col = colb + j * 8;
                const float* c = accf[i][j];
                *(float2*)(Cf + (size_t)r0 * ldc + col) =
                    make_float2(tanhf(c[0] + bias[col]), tanhf(c[1] + bias[col + 1]));
                *(float2*)(Cf + (size_t)(r0 + 8) * ldc + col) =
                    make_float2(tanhf(c[2] + bias[col]), tanhf(c[3] + bias[col + 1]));
            }
        }
    }
}

// ---------------- prep kernels ----------------
__global__ void roundH_kernel(const float* __restrict__ X0,
                              const float* __restrict__ X1,
                              const float* __restrict__ X2,
                              __half* __restrict__ Y, int per)
{
    const int zz = blockIdx.y;
    const float* X = (zz == 0) ? X0 : (zz == 1) ? X1 : X2;
    __half* Yz = Y + (size_t)zz * per;
    int i = (blockIdx.x * blockDim.x + threadIdx.x) * 4;
    if (i >= per) return;
    float4 v = *(const float4*)(X + i);
    __half2 a; a.x = __float2half_rn(v.x); a.y = __float2half_rn(v.y);
    __half2 b; b.x = __float2half_rn(v.z); b.y = __float2half_rn(v.w);
    *(__half2*)(Yz + i)     = a;
    *(__half2*)(Yz + i + 2) = b;
}

__global__ void round_kernel(const float* __restrict__ X,
                             __half* __restrict__ hi, int count)
{
    int i = (blockIdx.x * blockDim.x + threadIdx.x) * 4;
    if (i >= count) return;
    float4 v = *(const float4*)(X + i);
    __half2 a; a.x = __float2half_rn(v.x); a.y = __float2half_rn(v.y);
    __half2 b; b.x = __float2half_rn(v.z); b.y = __float2half_rn(v.w);
    *(__half2*)(hi + i)     = a;
    *(__half2*)(hi + i + 2) = b;
}

__global__ void round_t3_kernel(const float* __restrict__ X0,
                                const float* __restrict__ X1,
                                const float* __restrict__ X2,
                                __half* __restrict__ hT, int R, int C)
{
    __shared__ float tile[32][33];
    const int zz = blockIdx.z;
    const float* X = (zz == 0) ? X0 : (zz == 1) ? X1 : X2;
    __half* o = hT + (size_t)zz * R * C;
    const int c0 = blockIdx.x * 32;
    const int r0 = blockIdx.y * 32;
    const int tx = threadIdx.x;
    const int ty = threadIdx.y;
#pragma unroll
    for (int j = ty; j < 32; j += 8)
        tile[j][tx] = X[(size_t)(r0 + j) * C + c0 + tx];
    __syncthreads();
#pragma unroll
    for (int j = ty; j < 32; j += 8)
        o[(size_t)(c0 + j) * R + r0 + tx] = __float2half_rn(tile[tx][j]);
}

// row-major bit-pack of (X != 0): one warp per row. grid (rows/8, 2)
__global__ void bitpack_rows_kernel(const float* __restrict__ L,
                                    const float* __restrict__ Bh,
                                    uint32_t* __restrict__ Mb)
{
    const int z = blockIdx.y;                    // 0 -> L (slot 0), 1 -> B_high (slot 2)
    const float* X = z ? Bh : L;
    uint32_t* outb = Mb + (z ? 2 * MBZ : 0);
    const int row  = blockIdx.x * 8 + (threadIdx.x >> 5);
    const int lane = threadIdx.x & 31;
    const float* rp = X + (size_t)row * NDIM;
    uint32_t* op = outb + (size_t)row * 128;
#pragma unroll 4
    for (int w = 0; w < 128; w++) {
        const float v = rp[w * 32 + lane];
        const unsigned b = __ballot_sync(0xffffffffu, v != 0.f);
        if (lane == 0) op[w] = b;
    }
}

// transposed bit-pack: out[r] bit c = (B[c][r] != 0). grid (128,128), block (32,8)
__global__ void bitpack_T_kernel(const float* __restrict__ B,
                                 uint32_t* __restrict__ outb)
{
    __shared__ unsigned char tile[32][33];
    const int bx = blockIdx.x * 32;   // input cols = output rows
    const int by = blockIdx.y * 32;   // input rows = output bit positions
    const int tx = threadIdx.x;
    const int ty = threadIdx.y;
#pragma unroll
    for (int j = ty; j < 32; j += 8)
        tile[j][tx] = (B[(size_t)(by + j) * NDIM + bx + tx] != 0.f) ? 1 : 0;
    __syncthreads();
#pragma unroll
    for (int jj = 0; jj < 4; jj++) {
        const int ic = ty * 4 + jj;
        const unsigned bits = __ballot_sync(0xffffffffu, tile[tx][ic] != 0);
        if (tx == 0) outb[(size_t)(bx + ic) * 128 + (by >> 5)] = bits;
    }
}

// ============================================================================
// merged double softmax with bit mask; fp16 in/out (in place), grid (NDIM, 3)
// ============================================================================
__device__ __forceinline__ float warp_red_max(float v) {
#pragma unroll
    for (int o = 16; o; o >>= 1) v = fmaxf(v, __shfl_xor_sync(0xffffffffu, v, o));
    return v;
}
__device__ __forceinline__ float warp_red_sum(float v) {
#pragma unroll
    for (int o = 16; o; o >>= 1) v += __shfl_xor_sync(0xffffffffu, v, o);
    return v;
}
template <bool IS_MAX>
__device__ __forceinline__ float block_red(float v, float* red, int t) {
    v = IS_MAX ? warp_red_max(v) : warp_red_sum(v);
    __syncthreads();
    if ((t & 31) == 0) red[t >> 5] = v;
    __syncthreads();
    if (t < 32) {
        float x = (t < 8) ? red[t] : (IS_MAX ? -INFINITY : 0.f);
        x = IS_MAX ? warp_red_max(x) : warp_red_sum(x);
        if (t == 0) red[0] = x;
    }
    __syncthreads();
    return red[0];
}

__global__ void __launch_bounds__(256) softmax2_kernel(
    __half* __restrict__ Sbase, const uint32_t* __restrict__ Mb)
{
    __shared__ float red[32];
    const int t = threadIdx.x;
    const size_t row = blockIdx.x;
    const int z = blockIdx.y;
    __half* Srow = Sbase + (size_t)z * NN + row * NDIM;
    const uint32_t* mb = Mb + (size_t)z * MBZ + row * 128;

    float r[16];
    float mx = -INFINITY;
#pragma unroll
    for (int c = 0; c < 2; c++) {
        uint4 raw = *(const uint4*)(Srow + c * 2048 + t * 8);
        const __half2* h2 = (const __half2*)&raw;
#pragma unroll
        for (int q = 0; q < 4; q++) {
            float2 f = __half22float2(h2[q]);
            r[c*8 + 2*q]     = f.x;
            r[c*8 + 2*q + 1] = f.y;
            mx = fmaxf(mx, fmaxf(f.x, f.y));
        }
    }
    const float smax = block_red<true>(mx, red, t);

    float sum = 0.f;
#pragma unroll
    for (int i = 0; i < 16; i++) { r[i] = __expf(r[i] - smax); sum += r[i]; }
    const float inv = 1.f / block_red<false>(sum, red, t);

    float mx2 = -INFINITY;
#pragma unroll
    for (int c = 0; c < 2; c++) {
        const uint32_t w = __ldg(&mb[c * 64 + (t >> 2)]);
        const uint32_t bits = (w >> ((t & 3) * 8)) & 0xFFu;
#pragma unroll
        for (int i = 0; i < 8; i++) {
            r[c*8 + i] = ((bits >> i) & 1u) ? (r[c*8 + i] * inv) : 0.f;
            mx2 = fmaxf(mx2, r[c*8 + i]);
        }
    }
    const float smax2 = block_red<true>(mx2, red, t);

    float sum2 = 0.f;
#pragma unroll
    for (int i = 0; i < 16; i++) { r[i] = __expf(r[i] - smax2); sum2 += r[i]; }
    const float inv2 = 1.f / block_red<false>(sum2, red, t);

#pragma unroll
    for (int c = 0; c < 2; c++) {
        uint4 raw;
        __half2* h2 = (__half2*)&raw;
#pragma unroll
        for (int q = 0; q < 4; q++) {
            h2[q].x = __float2half_rn(r[c*8 + 2*q]     * inv2);
            h2[q].y = __float2half_rn(r[c*8 + 2*q + 1] * inv2);
        }
        *(uint4*)(Srow + c * 2048 + t * 8) = raw;
    }
}

// ============================================================================
// launch (R13 topology; per-instantiation GEMM launch bounds)
// ============================================================================
extern "C" void kernel_launch(void* const* d_in, const int* in_sizes, int n_in,
                              void* d_out, int out_size)
{
    const float* L      = (const float*)d_in[0];
    const float* H      = (const float*)d_in[1];
    const float* B_low  = (const float*)d_in[2];
    const float* H_low  = (const float*)d_in[3];
    const float* B_high = (const float*)d_in[4];
    const float* H_high = (const float*)d_in[5];
    const float* W      = (const float*)d_in[6];
    const float* bvec   = (const float*)d_in[7];
    float* out = (float*)d_out;

    __half *Sh, *Hh, *HT, *H4, *Wh;
    uint32_t* Mb;
    cudaGetSymbolAddress((void**)&Sh, g_Sh);
    cudaGetSymbolAddress((void**)&Hh, g_Hh);
    cudaGetSymbolAddress((void**)&HT, g_HT);
    cudaGetSymbolAddress((void**)&H4, g_H4);
    cudaGetSymbolAddress((void**)&Wh, g_Wh);
    cudaGetSymbolAddress((void**)&Mb, g_Mb);

    const float scale = 0.03125f;  // 1/sqrt(1024)
    const int rt = 256;

    // [0] merged fp16 rounds of H tensors
    roundH_kernel<<<dim3((unsigned)(HSZ / 4 / rt), 3), rt>>>(H, H_low, H_high, Hh, (int)HSZ);
    // [1] bit masks for L and B_high (row-major)
    bitpack_rows_kernel<<<dim3(NDIM / 8, 2), 256>>>(L, B_high, Mb);
    // [2] transposed bit mask for B_low
    bitpack_T_kernel<<<dim3(NDIM / 32, NDIM / 32), dim3(32, 8)>>>(B_low, Mb + MBZ);

    // [3] merged score GEMM, f16 accumulators, 3 CTAs/SM
    gemm_tcore<true><<<dim3(NDIM / 128, NDIM / 128, 3), 256>>>(
        Hh, 0, DDIM, Hh, HSZ, DDIM,
        DDIM, 0, scale, Sh, nullptr, NN, NDIM, nullptr);

    // [4] merged double softmax (in place, fp16, bit masks)
    softmax2_kernel<<<dim3(NDIM, 3), 256>>>(Sh, Mb);

    // [5] merged transposed fp16 KV copies
    round_t3_kernel<<<dim3(DDIM / 32, NDIM / 32, 3), dim3(32, 8)>>>(
        H, H_low, H_high, HT, NDIM, DDIM);

    // [6] merged AV GEMM, f32 accumulators, 2 CTAs/SM
    gemm_tcore<false><<<dim3(DDIM / 128, NDIM / 128, 3), 256>>>(
        Sh, NN, NDIM, HT, HSZ, NDIM,
        NDIM, 0, 1.0f, H4, nullptr, DDIM, 3 * DDIM, nullptr);

    // [7] W fp16 round
    round_kernel<<<(int)((size_t)DDIM * 3 * DDIM / 4 / rt), rt>>>(
        W, Wh, (int)((size_t)DDIM * 3 * DDIM));

    // [8] output GEMM: out = tanh(H4 @ W^T + b)
    gemm_tcore<false><<<dim3(DDIM / 128, NDIM / 128, 1), 256>>>(
        H4, 0, 3 * DDIM, Wh, 0, 3 * DDIM,
        3 * DDIM, 1, 1.0f, nullptr, out, 0, DDIM, bvec);
}

// round 16
// speedup vs baseline: 1.4000x; 1.0625x over previous
#include <cuda_runtime.h>
#include <cuda_fp16.h>
#include <math.h>
#include <stdint.h>

#define NDIM 4096
#define DDIM 1024
#define HSZ ((size_t)NDIM * DDIM)
#define NN  ((size_t)NDIM * NDIM)
#define MBZ ((size_t)NDIM * 128)   // uint32 words per bit-mask matrix

// ---------------- scratch (device globals) ----------------
__device__ __half g_Sh[3 * NN];                    // fp16 scores -> probs (in place)
__device__ __half g_Hh[3 * HSZ];                   // fp16(H / H_low / H_high)
__device__ __half g_H4[(size_t)NDIM * 3 * DDIM];   // fp16 concat AV outputs
__device__ __half g_Wh[(size_t)DDIM * 3 * DDIM];   // fp16(W)
__device__ uint32_t g_Mb[3 * MBZ];                 // bit masks: z0=L, z1=(B_low!=0)^T, z2=B_high

// ---------------- PTX helpers (portable tier) ----------------
__device__ __forceinline__ uint32_t smem_u32(const void* p) {
    uint32_t a;
    asm("{ .reg .u64 t; cvta.to.shared.u64 t, %1; cvt.u32.u64 %0, t; }" : "=r"(a) : "l"(p));
    return a;
}
__device__ __forceinline__ void cp_async16(uint32_t dst, const void* src) {
    asm volatile("cp.async.cg.shared.global [%0], [%1], 16;" :: "r"(dst), "l"(src) : "memory");
}
__device__ __forceinline__ void cp_commit() {
    asm volatile("cp.async.commit_group;" ::: "memory");
}
template <int N>
__device__ __forceinline__ void cp_wait() {
    asm volatile("cp.async.wait_group %0;" :: "n"(N) : "memory");
}
__device__ __forceinline__ void ldsm4(uint32_t* d, uint32_t addr) {
    asm volatile("ldmatrix.sync.aligned.m8n8.x4.shared.b16 {%0,%1,%2,%3}, [%4];"
        : "=r"(d[0]), "=r"(d[1]), "=r"(d[2]), "=r"(d[3]) : "r"(addr));
}
__device__ __forceinline__ void ldsm4t(uint32_t* d, uint32_t addr) {
    asm volatile("ldmatrix.sync.aligned.m8n8.x4.trans.shared.b16 {%0,%1,%2,%3}, [%4];"
        : "=r"(d[0]), "=r"(d[1]), "=r"(d[2]), "=r"(d[3]) : "r"(addr));
}
__device__ __forceinline__ void mma_f32(float* c, const uint32_t* a, const uint32_t* b) {
    asm volatile("mma.sync.aligned.m16n8k16.row.col.f32.f16.f16.f32 "
        "{%0,%1,%2,%3}, {%4,%5,%6,%7}, {%8,%9}, {%0,%1,%2,%3};"
        : "+f"(c[0]), "+f"(c[1]), "+f"(c[2]), "+f"(c[3])
        : "r"(a[0]), "r"(a[1]), "r"(a[2]), "r"(a[3]), "r"(b[0]), "r"(b[1]));
}
__device__ __forceinline__ void mma_f16acc(uint32_t* c, const uint32_t* a, const uint32_t* b) {
    asm volatile("mma.sync.aligned.m16n8k16.row.col.f16.f16.f16.f16 "
        "{%0,%1}, {%2,%3,%4,%5}, {%6,%7}, {%0,%1};"
        : "+r"(c[0]), "+r"(c[1])
        : "r"(a[0]), "r"(a[1]), "r"(a[2]), "r"(a[3]), "r"(b[0]), "r"(b[1]));
}

// NT tiles: 128 rows x 64B (row-per-m/n, 32 fp16 along k), XOR swizzle.
__device__ __forceinline__ uint32_t soff64(int r, int c) {
    return (uint32_t)(r * 64 + ((c ^ ((r >> 1) & 3)) << 4));
}
// NN B tile: 32 k-rows x 256B (128 fp16 along n), XOR swizzle.
// Conflict-free: ldsm phase reads 8 k-rows same chunk -> 8 distinct banks groups;
// cp.async 8-lane groups write 8 consecutive chunks of one row -> distinct.
__device__ __forceinline__ uint32_t soff256(int r, int c) {
    return (uint32_t)(r * 256 + ((c ^ (r & 7)) << 4));
}

#define OPB (128 * 64)      // 8 KB; NN B tile is 32*256 = same 8 KB
#define STB (2 * OPB)
#define NST 3
#define BKE 32

// ============================================================================
// HMMA GEMM. ACC16: f16 accum (scores), 3 CTAs/SM. !ACC16: f32 accum, 2 CTAs/SM.
// BNN=false: B is [N,K] K-major (NT).  BNN=true: B is [K,N] row-major (NN),
//            loaded via ldmatrix.trans -- used by AV GEMM to read Hh directly.
// mode 0: Ch = fp16(alpha * acc)   mode 1 (!ACC16): Cf = tanh(acc + bias[n])
// ============================================================================
template <bool ACC16, bool BNN>
__global__ void __launch_bounds__(256, ACC16 ? 3 : 2) gemm_tcore(
    const __half* __restrict__ A, size_t sAz, int lda,
    const __half* __restrict__ B, size_t sBz, int ldb,
    int K, int mode, float alpha,
    __half* __restrict__ Ch, float* __restrict__ Cf, size_t sCz, int ldc,
    const float* __restrict__ bias)
{
    __shared__ __align__(128) char sm[NST * STB];

    const int t    = threadIdx.x;
    const int lane = t & 31;
    const int wid  = t >> 5;
    const int wm   = (wid & 3) * 32;
    const int wn   = (wid >> 2) * 64;
    const int m0   = blockIdx.y * 128;
    const int n0   = blockIdx.x * 128;
    const int z    = blockIdx.z;
    A += (size_t)z * sAz;
    B += (size_t)z * sBz;
    const uint32_t sbase = smem_u32(sm);

    // ---- A loader (both variants): 128 rows x 64B
    const int rl = t >> 2;
    const int cl = t & 3;
    const uint32_t stA0 = soff64(rl, cl);
    const uint32_t stA1 = soff64(rl + 64, cl);
    const __half* gA0 = A + (size_t)(m0 + rl) * lda + cl * 8;
    const __half* gA1 = A + (size_t)(m0 + rl + 64) * lda + cl * 8;

    // ---- B loader
    uint32_t stB0, stB1;
    const __half *gB0, *gB1;
    if (BNN) {
        const int bkr = t >> 4;        // k-row 0..15 (+16)
        const int bc  = t & 15;        // 16B chunk 0..15
        stB0 = soff256(bkr, bc);
        stB1 = soff256(bkr + 16, bc);
        gB0 = B + (size_t)bkr * ldb + n0 + bc * 8;
        gB1 = B + (size_t)(bkr + 16) * ldb + n0 + bc * 8;
    } else {
        stB0 = soff64(rl, cl);
        stB1 = soff64(rl + 64, cl);
        gB0 = B + (size_t)(n0 + rl) * ldb + cl * 8;
        gB1 = B + (size_t)(n0 + rl + 64) * ldb + cl * 8;
    }
    const size_t kBstep = BNN ? (size_t)BKE * ldb : (size_t)BKE;

    // ---- fragment smem offsets
    uint32_t adA[2][2], adB[2][4];
    {
        const int mm = lane >> 3;
#pragma unroll
        for (int ks = 0; ks < 2; ks++) {
#pragma unroll
            for (int i = 0; i < 2; i++)
                adA[ks][i] = soff64(wm + i * 16 + (mm & 1) * 8 + (lane & 7),
                                    2 * ks + (mm >> 1));
            if (BNN) {
                const int mr = lane & 7;
#pragma unroll
                for (int j = 0; j < 4; j++)
                    adB[ks][j] = soff256(ks * 16 + (mm & 1) * 8 + mr,
                                         (wn >> 3) + j * 2 + (mm >> 1));
            } else {
#pragma unroll
                for (int j = 0; j < 4; j++)
                    adB[ks][j] = soff64(wn + j * 16 + (mm >> 1) * 8 + (lane & 7),
                                        2 * ks + (mm & 1));
            }
        }
    }

    float    accf[2][8][4];
    uint32_t acch[2][8][2];
#pragma unroll
    for (int i = 0; i < 2; i++)
#pragma unroll
        for (int j = 0; j < 8; j++) {
            if (ACC16) { acch[i][j][0] = 0u; acch[i][j][1] = 0u; }
            else {
#pragma unroll
                for (int q = 0; q < 4; q++) accf[i][j][q] = 0.f;
            }
        }

    const int T = K / BKE;

#pragma unroll
    for (int s = 0; s < NST - 1; s++) {
        const uint32_t d = sbase + s * STB;
        cp_async16(d + stA0,       gA0 + (size_t)s * BKE);
        cp_async16(d + stA1,       gA1 + (size_t)s * BKE);
        cp_async16(d + OPB + stB0, gB0 + (size_t)s * kBstep);
        cp_async16(d + OPB + stB1, gB1 + (size_t)s * kBstep);
        cp_commit();
    }

    for (int tt = 0; tt < T; tt++) {
        __syncthreads();
        const int nt = tt + NST - 1;
        if (nt < T) {
            const uint32_t d = sbase + (nt % NST) * STB;
            cp_async16(d + stA0,       gA0 + (size_t)nt * BKE);
            cp_async16(d + stA1,       gA1 + (size_t)nt * BKE);
            cp_async16(d + OPB + stB0, gB0 + (size_t)nt * kBstep);
            cp_async16(d + OPB + stB1, gB1 + (size_t)nt * kBstep);
        }
        cp_commit();
        cp_wait<NST - 2>();
        __syncthreads();

        const uint32_t sb = sbase + (tt % NST) * STB;
#pragma unroll
        for (int ks = 0; ks < 2; ks++) {
            uint32_t a[2][4], b[8][2];
            ldsm4(a[0], sb + adA[ks][0]);
            ldsm4(a[1], sb + adA[ks][1]);
#pragma unroll
            for (int j = 0; j < 4; j++) {
                uint32_t tmp[4];
                if (BNN) ldsm4t(tmp, sb + OPB + adB[ks][j]);
                else     ldsm4 (tmp, sb + OPB + adB[ks][j]);
                b[2*j][0]   = tmp[0]; b[2*j][1]   = tmp[1];
                b[2*j+1][0] = tmp[2]; b[2*j+1][1] = tmp[3];
            }
#pragma unroll
            for (int i = 0; i < 2; i++)
#pragma unroll
                for (int j = 0; j < 8; j++) {
                    if (ACC16) mma_f16acc(acch[i][j], a[i], b[j]);
                    else       mma_f32  (accf[i][j], a[i], b[j]);
                }
        }
    }

    const int row0 = m0 + wm + (lane >> 2);
    const int colb = n0 + wn + (lane & 3) * 2;
    if (ACC16) {
        __half* Cz = Ch + (size_t)z * sCz;
        const __half2 sc2 = __float2half2_rn(alpha);
#pragma unroll
        for (int i = 0; i < 2; i++) {
#pragma unroll
            for (int j = 0; j < 8; j++) {
                const int r0 = row0 + i * 16;
                const int col = colb + j * 8;
                *(__half2*)(Cz + (size_t)r0 * ldc + col)       = __hmul2(*(__half2*)&acch[i][j][0], sc2);
                *(__half2*)(Cz + (size_t)(r0 + 8) * ldc + col) = __hmul2(*(__half2*)&acch[i][j][1], sc2);
            }
        }
    } else if (mode == 0) {
        __half* Cz = Ch + (size_t)z * sCz;
#pragma unroll
        for (int i = 0; i < 2; i++) {
#pragma unroll
            for (int j = 0; j < 8; j++) {
                const int r0 = row0 + i * 16;
                const int col = colb + j * 8;
                const float* c = accf[i][j];
                __half2 v0; v0.x = __float2half_rn(c[0]); v0.y = __float2half_rn(c[1]);
                __half2 v1; v1.x = __float2half_rn(c[2]); v1.y = __float2half_rn(c[3]);
                *(__half2*)(Cz + (size_t)r0 * ldc + col)       = v0;
                *(__half2*)(Cz + (size_t)(r0 + 8) * ldc + col) = v1;
            }
        }
    } else {
#pragma unroll
        for (int i = 0; i < 2; i++) {
#pragma unroll
            for (int j = 0; j < 8; j++) {
                const int r0 = row0 + i * 16;
                const int col = colb + j * 8;
                const float* c = accf[i][j];
                *(float2*)(Cf + (size_t)r0 * ldc + col) =
                    make_float2(tanhf(c[0] + bias[col]), tanhf(c[1] + bias[col + 1]));
                *(float2*)(Cf + (size_t)(r0 + 8) * ldc + col) =
                    make_float2(tanhf(c[2] + bias[col]), tanhf(c[3] + bias[col + 1]));
            }
        }
    }
}

// ---------------- prep kernels ----------------
__global__ void roundH_kernel(const float* __restrict__ X0,
                              const float* __restrict__ X1,
                              const float* __restrict__ X2,
                              __half* __restrict__ Y, int per)
{
    const int zz = blockIdx.y;
    const float* X = (zz == 0) ? X0 : (zz == 1) ? X1 : X2;
    __half* Yz = Y + (size_t)zz * per;
    int i = (blockIdx.x * blockDim.x + threadIdx.x) * 4;
    if (i >= per) return;
    float4 v = *(const float4*)(X + i);
    __half2 a; a.x = __float2half_rn(v.x); a.y = __float2half_rn(v.y);
    __half2 b; b.x = __float2half_rn(v.z); b.y = __float2half_rn(v.w);
    *(__half2*)(Yz + i)     = a;
    *(__half2*)(Yz + i + 2) = b;
}

__global__ void round_kernel(const float* __restrict__ X,
                             __half* __restrict__ hi, int count)
{
    int i = (blockIdx.x * blockDim.x + threadIdx.x) * 4;
    if (i >= count) return;
    float4 v = *(const float4*)(X + i);
    __half2 a; a.x = __float2half_rn(v.x); a.y = __float2half_rn(v.y);
    __half2 b; b.x = __float2half_rn(v.z); b.y = __float2half_rn(v.w);
    *(__half2*)(hi + i)     = a;
    *(__half2*)(hi + i + 2) = b;
}

// row-major bit-pack of (X != 0): one warp per row. grid (rows/8, 2)
__global__ void bitpack_rows_kernel(const float* __restrict__ L,
                                    const float* __restrict__ Bh,
                                    uint32_t* __restrict__ Mb)
{
    const int z = blockIdx.y;                    // 0 -> L (slot 0), 1 -> B_high (slot 2)
    const float* X = z ? Bh : L;
    uint32_t* outb = Mb + (z ? 2 * MBZ : 0);
    const int row  = blockIdx.x * 8 + (threadIdx.x >> 5);
    const int lane = threadIdx.x & 31;
    const float* rp = X + (size_t)row * NDIM;
    uint32_t* op = outb + (size_t)row * 128;
#pragma unroll 4
    for (int w = 0; w < 128; w++) {
        const float v = rp[w * 32 + lane];
        const unsigned b = __ballot_sync(0xffffffffu, v != 0.f);
        if (lane == 0) op[w] = b;
    }
}

// transposed bit-pack: out[r] bit c = (B[c][r] != 0). grid (128,128), block (32,8)
__global__ void bitpack_T_kernel(const float* __restrict__ B,
                                 uint32_t* __restrict__ outb)
{
    __shared__ unsigned char tile[32][33];
    const int bx = blockIdx.x * 32;   // input cols = output rows
    const int by = blockIdx.y * 32;   // input rows = output bit positions
    const int tx = threadIdx.x;
    const int ty = threadIdx.y;
#pragma unroll
    for (int j = ty; j < 32; j += 8)
        tile[j][tx] = (B[(size_t)(by + j) * NDIM + bx + tx] != 0.f) ? 1 : 0;
    __syncthreads();
#pragma unroll
    for (int jj = 0; jj < 4; jj++) {
        const int ic = ty * 4 + jj;
        const unsigned bits = __ballot_sync(0xffffffffu, tile[tx][ic] != 0);
        if (tx == 0) outb[(size_t)(bx + ic) * 128 + (by >> 5)] = bits;
    }
}

// ============================================================================
// merged double softmax with bit mask; fp16 in/out (in place), grid (NDIM, 3)
// ============================================================================
__device__ __forceinline__ float warp_red_max(float v) {
#pragma unroll
    for (int o = 16; o; o >>= 1) v = fmaxf(v, __shfl_xor_sync(0xffffffffu, v, o));
    return v;
}
__device__ __forceinline__ float warp_red_sum(float v) {
#pragma unroll
    for (int o = 16; o; o >>= 1) v += __shfl_xor_sync(0xffffffffu, v, o);
    return v;
}
template <bool IS_MAX>
__device__ __forceinline__ float block_red(float v, float* red, int t) {
    v = IS_MAX ? warp_red_max(v) : warp_red_sum(v);
    __syncthreads();
    if ((t & 31) == 0) red[t >> 5] = v;
    __syncthreads();
    if (t < 32) {
        float x = (t < 8) ? red[t] : (IS_MAX ? -INFINITY : 0.f);
        x = IS_MAX ? warp_red_max(x) : warp_red_sum(x);
        if (t == 0) red[0] = x;
    }
    __syncthreads();
    return red[0];
}

__global__ void __launch_bounds__(256) softmax2_kernel(
    __half* __restrict__ Sbase, const uint32_t* __restrict__ Mb)
{
    __shared__ float red[32];
    const int t = threadIdx.x;
    const size_t row = blockIdx.x;
    const int z = blockIdx.y;
    __half* Srow = Sbase + (size_t)z * NN + row * NDIM;
    const uint32_t* mb = Mb + (size_t)z * MBZ + row * 128;

    float r[16];
    float mx = -INFINITY;
#pragma unroll
    for (int c = 0; c < 2; c++) {
        uint4 raw = *(const uint4*)(Srow + c * 2048 + t * 8);
        const __half2* h2 = (const __half2*)&raw;
#pragma unroll
        for (int q = 0; q < 4; q++) {
            float2 f = __half22float2(h2[q]);
            r[c*8 + 2*q]     = f.x;
            r[c*8 + 2*q + 1] = f.y;
            mx = fmaxf(mx, fmaxf(f.x, f.y));
        }
    }
    const float smax = block_red<true>(mx, red, t);

    float sum = 0.f;
#pragma unroll
    for (int i = 0; i < 16; i++) { r[i] = __expf(r[i] - smax); sum += r[i]; }
    const float inv = 1.f / block_red<false>(sum, red, t);

    float mx2 = -INFINITY;
#pragma unroll
    for (int c = 0; c < 2; c++) {
        const uint32_t w = __ldg(&mb[c * 64 + (t >> 2)]);
        const uint32_t bits = (w >> ((t & 3) * 8)) & 0xFFu;
#pragma unroll
        for (int i = 0; i < 8; i++) {
            r[c*8 + i] = ((bits >> i) & 1u) ? (r[c*8 + i] * inv) : 0.f;
            mx2 = fmaxf(mx2, r[c*8 + i]);
        }
    }
    const float smax2 = block_red<true>(mx2, red, t);

    float sum2 = 0.f;
#pragma unroll
    for (int i = 0; i < 16; i++) { r[i] = __expf(r[i] - smax2); sum2 += r[i]; }
    const float inv2 = 1.f / block_red<false>(sum2, red, t);

#pragma unroll
    for (int c = 0; c < 2; c++) {
        uint4 raw;
        __half2* h2 = (__half2*)&raw;
#pragma unroll
        for (int q = 0; q < 4; q++) {
            h2[q].x = __float2half_rn(r[c*8 + 2*q]     * inv2);
            h2[q].y = __float2half_rn(r[c*8 + 2*q + 1] * inv2);
        }
        *(uint4*)(Srow + c * 2048 + t * 8) = raw;
    }
}

// ============================================================================
// launch (R15 topology; AV GEMM now reads Hh directly via NN path)
// ============================================================================
extern "C" void kernel_launch(void* const* d_in, const int* in_sizes, int n_in,
                              void* d_out, int out_size)
{
    const float* L      = (const float*)d_in[0];
    const float* H      = (const float*)d_in[1];
    const float* B_low  = (const float*)d_in[2];
    const float* H_low  = (const float*)d_in[3];
    const float* B_high = (const float*)d_in[4];
    const float* H_high = (const float*)d_in[5];
    const float* W      = (const float*)d_in[6];
    const float* bvec   = (const float*)d_in[7];
    float* out = (float*)d_out;

    __half *Sh, *Hh, *H4, *Wh;
    uint32_t* Mb;
    cudaGetSymbolAddress((void**)&Sh, g_Sh);
    cudaGetSymbolAddress((void**)&Hh, g_Hh);
    cudaGetSymbolAddress((void**)&H4, g_H4);
    cudaGetSymbolAddress((void**)&Wh, g_Wh);
    cudaGetSymbolAddress((void**)&Mb, g_Mb);

    const float scale = 0.03125f;  // 1/sqrt(1024)
    const int rt = 256;

    // [0] merged fp16 rounds of H tensors
    roundH_kernel<<<dim3((unsigned)(HSZ / 4 / rt), 3), rt>>>(H, H_low, H_high, Hh, (int)HSZ);
    // [1] bit masks for L and B_high (row-major)
    bitpack_rows_kernel<<<dim3(NDIM / 8, 2), 256>>>(L, B_high, Mb);
    // [2] transposed bit mask for B_low
    bitpack_T_kernel<<<dim3(NDIM / 32, NDIM / 32), dim3(32, 8)>>>(B_low, Mb + MBZ);

    // [3] merged score GEMM, f16 accumulators, 3 CTAs/SM (NT)
    gemm_tcore<true, false><<<dim3(NDIM / 128, NDIM / 128, 3), 256>>>(
        Hh, 0, DDIM, Hh, HSZ, DDIM,
        DDIM, 0, scale, Sh, nullptr, NN, NDIM, nullptr);

    // [4] merged double softmax (in place, fp16, bit masks)
    softmax2_kernel<<<dim3(NDIM, 3), 256>>>(Sh, Mb);

    // [5] merged AV GEMM, f32 accumulators, NN path: B = Hh [token][feature]
    gemm_tcore<false, true><<<dim3(DDIM / 128, NDIM / 128, 3), 256>>>(
        Sh, NN, NDIM, Hh, HSZ, DDIM,
        NDIM, 0, 1.0f, H4, nullptr, DDIM, 3 * DDIM, nullptr);

    // [6] W fp16 round
    round_kernel<<<(int)((size_t)DDIM * 3 * DDIM / 4 / rt), rt>>>(
        W, Wh, (int)((size_t)DDIM * 3 * DDIM));

    // [7] output GEMM: out = tanh(H4 @ W^T + b)  (NT)
    gemm_tcore<false, false><<<dim3(DDIM / 128, NDIM / 128, 1), 256>>>(
        H4, 0, 3 * DDIM, Wh, 0, 3 * DDIM,
        3 * DDIM, 1, 1.0f, nullptr, out, 0, DDIM, bvec);
}

// round 17
// speedup vs baseline: 1.4688x; 1.0491x over previous
#include <cuda_runtime.h>
#include <cuda_fp16.h>
#include <math.h>
#include <stdint.h>

#define NDIM 4096
#define DDIM 1024
#define HSZ ((size_t)NDIM * DDIM)
#define NN  ((size_t)NDIM * NDIM)
#define MBZ ((size_t)NDIM * 128)   // uint32 words per bit-mask matrix

// ---------------- scratch (device globals) ----------------
__device__ __half g_Sh[3 * NN];                    // fp16 scores -> probs (in place)
__device__ __half g_Hh[3 * HSZ];                   // fp16(H / H_low / H_high)
__device__ __half g_H4[(size_t)NDIM * 3 * DDIM];   // fp16 concat AV outputs
__device__ __half g_Wh[(size_t)DDIM * 3 * DDIM];   // fp16(W)
__device__ uint32_t g_Mb[3 * MBZ];                 // bit masks: z0=L, z1=(B_low!=0)^T, z2=B_high

// ---------------- PTX helpers (portable tier) ----------------
__device__ __forceinline__ uint32_t smem_u32(const void* p) {
    uint32_t a;
    asm("{ .reg .u64 t; cvta.to.shared.u64 t, %1; cvt.u32.u64 %0, t; }" : "=r"(a) : "l"(p));
    return a;
}
__device__ __forceinline__ void cp_async16(uint32_t dst, const void* src) {
    asm volatile("cp.async.cg.shared.global [%0], [%1], 16;" :: "r"(dst), "l"(src) : "memory");
}
__device__ __forceinline__ void cp_commit() {
    asm volatile("cp.async.commit_group;" ::: "memory");
}
template <int N>
__device__ __forceinline__ void cp_wait() {
    asm volatile("cp.async.wait_group %0;" :: "n"(N) : "memory");
}
__device__ __forceinline__ void ldsm4(uint32_t* d, uint32_t addr) {
    asm volatile("ldmatrix.sync.aligned.m8n8.x4.shared.b16 {%0,%1,%2,%3}, [%4];"
        : "=r"(d[0]), "=r"(d[1]), "=r"(d[2]), "=r"(d[3]) : "r"(addr));
}
__device__ __forceinline__ void ldsm4t(uint32_t* d, uint32_t addr) {
    asm volatile("ldmatrix.sync.aligned.m8n8.x4.trans.shared.b16 {%0,%1,%2,%3}, [%4];"
        : "=r"(d[0]), "=r"(d[1]), "=r"(d[2]), "=r"(d[3]) : "r"(addr));
}
__device__ __forceinline__ void mma_f32(float* c, const uint32_t* a, const uint32_t* b) {
    asm volatile("mma.sync.aligned.m16n8k16.row.col.f32.f16.f16.f32 "
        "{%0,%1,%2,%3}, {%4,%5,%6,%7}, {%8,%9}, {%0,%1,%2,%3};"
        : "+f"(c[0]), "+f"(c[1]), "+f"(c[2]), "+f"(c[3])
        : "r"(a[0]), "r"(a[1]), "r"(a[2]), "r"(a[3]), "r"(b[0]), "r"(b[1]));
}
__device__ __forceinline__ void mma_f16acc(uint32_t* c, const uint32_t* a, const uint32_t* b) {
    asm volatile("mma.sync.aligned.m16n8k16.row.col.f16.f16.f16.f16 "
        "{%0,%1}, {%2,%3,%4,%5}, {%6,%7}, {%0,%1};"
        : "+r"(c[0]), "+r"(c[1])
        : "r"(a[0]), "r"(a[1]), "r"(a[2]), "r"(a[3]), "r"(b[0]), "r"(b[1]));
}

// NT tiles: 128 rows x 64B (row-per-m/n, 32 fp16 along k), XOR swizzle.
__device__ __forceinline__ uint32_t soff64(int r, int c) {
    return (uint32_t)(r * 64 + ((c ^ ((r >> 1) & 3)) << 4));
}
// NN B tile: 32 k-rows x 256B (128 fp16 along n), XOR swizzle.
__device__ __forceinline__ uint32_t soff256(int r, int c) {
    return (uint32_t)(r * 256 + ((c ^ (r & 7)) << 4));
}

#define OPB (128 * 64)      // 8 KB per operand per stage
#define STB (2 * OPB)
#define NST 3
#define BKE 32
#define TPAD 136            // transposed-tile smem row pitch (halves); 272B = 16B-aligned

// ============================================================================
// HMMA GEMM. ACC16: f16 accum (scores), 3 CTAs/SM. !ACC16: f32 accum, 2 CTAs/SM.
// BNN: B operand is [K,N] row-major via ldmatrix.trans (AV reads Hh directly).
// sym: z==0 operand pair is symmetric -> compute upper triangle only, mirror.
// mode 0: Ch = fp16(alpha * acc)   mode 1 (!ACC16): Cf = tanh(acc + bias[n])
// ============================================================================
template <bool ACC16, bool BNN>
__global__ void __launch_bounds__(256, ACC16 ? 3 : 2) gemm_tcore(
    const __half* __restrict__ A, size_t sAz, int lda,
    const __half* __restrict__ B, size_t sBz, int ldb,
    int K, int mode, float alpha,
    __half* __restrict__ Ch, float* __restrict__ Cf, size_t sCz, int ldc,
    const float* __restrict__ bias, int sym)
{
    __shared__ __align__(128) char sm[NST * STB];

    const int z = blockIdx.z;
    // symmetric branch: skip lower-triangle tiles
    if (sym && z == 0 && blockIdx.x < blockIdx.y) return;

    const int t    = threadIdx.x;
    const int lane = t & 31;
    const int wid  = t >> 5;
    const int wm   = (wid & 3) * 32;
    const int wn   = (wid >> 2) * 64;
    const int m0   = blockIdx.y * 128;
    const int n0   = blockIdx.x * 128;
    A += (size_t)z * sAz;
    B += (size_t)z * sBz;
    const uint32_t sbase = smem_u32(sm);

    // ---- A loader: 128 rows x 64B
    const int rl = t >> 2;
    const int cl = t & 3;
    const uint32_t stA0 = soff64(rl, cl);
    const uint32_t stA1 = soff64(rl + 64, cl);
    const __half* gA0 = A + (size_t)(m0 + rl) * lda + cl * 8;
    const __half* gA1 = A + (size_t)(m0 + rl + 64) * lda + cl * 8;

    // ---- B loader
    uint32_t stB0, stB1;
    const __half *gB0, *gB1;
    if (BNN) {
        const int bkr = t >> 4;
        const int bc  = t & 15;
        stB0 = soff256(bkr, bc);
        stB1 = soff256(bkr + 16, bc);
        gB0 = B + (size_t)bkr * ldb + n0 + bc * 8;
        gB1 = B + (size_t)(bkr + 16) * ldb + n0 + bc * 8;
    } else {
        stB0 = soff64(rl, cl);
        stB1 = soff64(rl + 64, cl);
        gB0 = B + (size_t)(n0 + rl) * ldb + cl * 8;
        gB1 = B + (size_t)(n0 + rl + 64) * ldb + cl * 8;
    }
    const size_t kBstep = BNN ? (size_t)BKE * ldb : (size_t)BKE;

    // ---- fragment smem offsets
    uint32_t adA[2][2], adB[2][4];
    {
        const int mm = lane >> 3;
#pragma unroll
        for (int ks = 0; ks < 2; ks++) {
#pragma unroll
            for (int i = 0; i < 2; i++)
                adA[ks][i] = soff64(wm + i * 16 + (mm & 1) * 8 + (lane & 7),
                                    2 * ks + (mm >> 1));
            if (BNN) {
                const int mr = lane & 7;
#pragma unroll
                for (int j = 0; j < 4; j++)
                    adB[ks][j] = soff256(ks * 16 + (mm & 1) * 8 + mr,
                                         (wn >> 3) + j * 2 + (mm >> 1));
            } else {
#pragma unroll
                for (int j = 0; j < 4; j++)
                    adB[ks][j] = soff64(wn + j * 16 + (mm >> 1) * 8 + (lane & 7),
                                        2 * ks + (mm & 1));
            }
        }
    }

    float    accf[2][8][4];
    uint32_t acch[2][8][2];
#pragma unroll
    for (int i = 0; i < 2; i++)
#pragma unroll
        for (int j = 0; j < 8; j++) {
            if (ACC16) { acch[i][j][0] = 0u; acch[i][j][1] = 0u; }
            else {
#pragma unroll
                for (int q = 0; q < 4; q++) accf[i][j][q] = 0.f;
            }
        }

    const int T = K / BKE;

#pragma unroll
    for (int s = 0; s < NST - 1; s++) {
        const uint32_t d = sbase + s * STB;
        cp_async16(d + stA0,       gA0 + (size_t)s * BKE);
        cp_async16(d + stA1,       gA1 + (size_t)s * BKE);
        cp_async16(d + OPB + stB0, gB0 + (size_t)s * kBstep);
        cp_async16(d + OPB + stB1, gB1 + (size_t)s * kBstep);
        cp_commit();
    }

    for (int tt = 0; tt < T; tt++) {
        __syncthreads();
        const int nt = tt + NST - 1;
        if (nt < T) {
            const uint32_t d = sbase + (nt % NST) * STB;
            cp_async16(d + stA0,       gA0 + (size_t)nt * BKE);
            cp_async16(d + stA1,       gA1 + (size_t)nt * BKE);
            cp_async16(d + OPB + stB0, gB0 + (size_t)nt * kBstep);
            cp_async16(d + OPB + stB1, gB1 + (size_t)nt * kBstep);
        }
        cp_commit();
        cp_wait<NST - 2>();
        __syncthreads();

        const uint32_t sb = sbase + (tt % NST) * STB;
#pragma unroll
        for (int ks = 0; ks < 2; ks++) {
            uint32_t a[2][4], b[8][2];
            ldsm4(a[0], sb + adA[ks][0]);
            ldsm4(a[1], sb + adA[ks][1]);
#pragma unroll
            for (int j = 0; j < 4; j++) {
                uint32_t tmp[4];
                if (BNN) ldsm4t(tmp, sb + OPB + adB[ks][j]);
                else     ldsm4 (tmp, sb + OPB + adB[ks][j]);
                b[2*j][0]   = tmp[0]; b[2*j][1]   = tmp[1];
                b[2*j+1][0] = tmp[2]; b[2*j+1][1] = tmp[3];
            }
#pragma unroll
            for (int i = 0; i < 2; i++)
#pragma unroll
                for (int j = 0; j < 8; j++) {
                    if (ACC16) mma_f16acc(acch[i][j], a[i], b[j]);
                    else       mma_f32  (accf[i][j], a[i], b[j]);
                }
        }
    }

    const int row0 = m0 + wm + (lane >> 2);
    const int colb = n0 + wn + (lane & 3) * 2;
    if (ACC16) {
        __half* Cz = Ch + (size_t)z * sCz;
        const __half2 sc2 = __float2half2_rn(alpha);
#pragma unroll
        for (int i = 0; i < 2; i++) {
#pragma unroll
            for (int j = 0; j < 8; j++) {
                const int r0 = row0 + i * 16;
                const int col = colb + j * 8;
                *(__half2*)(Cz + (size_t)r0 * ldc + col)       = __hmul2(*(__half2*)&acch[i][j][0], sc2);
                *(__half2*)(Cz + (size_t)(r0 + 8) * ldc + col) = __hmul2(*(__half2*)&acch[i][j][1], sc2);
            }
        }
        // ---- symmetric mirror: write transpose of this tile to block (n0, m0)
        if (sym && z == 0 && n0 > m0) {
            cp_wait<0>();
            __syncthreads();                 // pipeline smem now free
            __half* smT = (__half*)sm;       // [128][TPAD] halves = 34,816 B
            const int lr0 = wm + (lane >> 2);          // tile-local row
            const int lc0 = wn + (lane & 3) * 2;       // tile-local col
#pragma unroll
            for (int i = 0; i < 2; i++) {
#pragma unroll
                for (int j = 0; j < 8; j++) {
                    const int r = lr0 + i * 16;
                    const int c = lc0 + j * 8;
                    __half2 v0 = __hmul2(*(__half2*)&acch[i][j][0], sc2);
                    __half2 v1 = __hmul2(*(__half2*)&acch[i][j][1], sc2);
                    smT[(size_t)c       * TPAD + r]     = v0.x;
                    smT[(size_t)(c + 1) * TPAD + r]     = v0.y;
                    smT[(size_t)c       * TPAD + r + 8] = v1.x;
                    smT[(size_t)(c + 1) * TPAD + r + 8] = v1.y;
                }
            }
            __syncthreads();
            const int rr  = t >> 1;                    // mirror-block row 0..127
            const int off = (t & 1) * 64;              // half offset 0 / 64
            const uint4* src = (const uint4*)(smT + (size_t)rr * TPAD + off);
            __half* dst = Cz + (size_t)(n0 + rr) * ldc + m0 + off;
#pragma unroll
            for (int k = 0; k < 8; k++)
                *(uint4*)(dst + k * 8) = src[k];
        }
    } else if (mode == 0) {
        __half* Cz = Ch + (size_t)z * sCz;
#pragma unroll
        for (int i = 0; i < 2; i++) {
#pragma unroll
            for (int j = 0; j < 8; j++) {
                const int r0 = row0 + i * 16;
                const int col = colb + j * 8;
                const float* c = accf[i][j];
                __half2 v0; v0.x = __float2half_rn(c[0]); v0.y = __float2half_rn(c[1]);
                __half2 v1; v1.x = __float2half_rn(c[2]); v1.y = __float2half_rn(c[3]);
                *(__half2*)(Cz + (size_t)r0 * ldc + col)       = v0;
                *(__half2*)(Cz + (size_t)(r0 + 8) * ldc + col) = v1;
            }
        }
    } else {
#pragma unroll
        for (int i = 0; i < 2; i++) {
#pragma unroll
            for (int j = 0; j < 8; j++) {
                const int r0 = row0 + i * 16;
                const int col = colb + j * 8;
                const float* c = accf[i][j];
                *(float2*)(Cf + (size_t)r0 * ldc + col) =
                    make_float2(tanhf(c[0] + bias[col]), tanhf(c[1] + bias[col + 1]));
                *(float2*)(Cf + (size_t)(r0 + 8) * ldc + col) =
                    make_float2(tanhf(c[2] + bias[col]), tanhf(c[3] + bias[col + 1]));
            }
        }
    }
}

// ---------------- prep kernels ----------------
__global__ void roundH_kernel(const float* __restrict__ X0,
                              const float* __restrict__ X1,
                              const float* __restrict__ X2,
                              __half* __restrict__ Y, int per)
{
    const int zz = blockIdx.y;
    const float* X = (zz == 0) ? X0 : (zz == 1) ? X1 : X2;
    __half* Yz = Y + (size_t)zz * per;
    int i = (blockIdx.x * blockDim.x + threadIdx.x) * 4;
    if (i >= per) return;
    float4 v = *(const float4*)(X + i);
    __half2 a; a.x = __float2half_rn(v.x); a.y = __float2half_rn(v.y);
    __half2 b; b.x = __float2half_rn(v.z); b.y = __float2half_rn(v.w);
    *(__half2*)(Yz + i)     = a;
    *(__half2*)(Yz + i + 2) = b;
}

__global__ void round_kernel(const float* __restrict__ X,
                             __half* __restrict__ hi, int count)
{
    int i = (blockIdx.x * blockDim.x + threadIdx.x) * 4;
    if (i >= count) return;
    float4 v = *(const float4*)(X + i);
    __half2 a; a.x = __float2half_rn(v.x); a.y = __float2half_rn(v.y);
    __half2 b; b.x = __float2half_rn(v.z); b.y = __float2half_rn(v.w);
    *(__half2*)(hi + i)     = a;
    *(__half2*)(hi + i + 2) = b;
}

// row-major bit-pack of (X != 0): one warp per row. grid (rows/8, 2)
__global__ void bitpack_rows_kernel(const float* __restrict__ L,
                                    const float* __restrict__ Bh,
                                    uint32_t* __restrict__ Mb)
{
    const int z = blockIdx.y;                    // 0 -> L (slot 0), 1 -> B_high (slot 2)
    const float* X = z ? Bh : L;
    uint32_t* outb = Mb + (z ? 2 * MBZ : 0);
    const int row  = blockIdx.x * 8 + (threadIdx.x >> 5);
    const int lane = threadIdx.x & 31;
    const float* rp = X + (size_t)row * NDIM;
    uint32_t* op = outb + (size_t)row * 128;
#pragma unroll 4
    for (int w = 0; w < 128; w++) {
        const float v = rp[w * 32 + lane];
        const unsigned b = __ballot_sync(0xffffffffu, v != 0.f);
        if (lane == 0) op[w] = b;
    }
}

// transposed bit-pack: out[r] bit c = (B[c][r] != 0). grid (128,128), block (32,8)
__global__ void bitpack_T_kernel(const float* __restrict__ B,
                                 uint32_t* __restrict__ outb)
{
    __shared__ unsigned char tile[32][33];
    const int bx = blockIdx.x * 32;
    const int by = blockIdx.y * 32;
    const int tx = threadIdx.x;
    const int ty = threadIdx.y;
#pragma unroll
    for (int j = ty; j < 32; j += 8)
        tile[j][tx] = (B[(size_t)(by + j) * NDIM + bx + tx] != 0.f) ? 1 : 0;
    __syncthreads();
#pragma unroll
    for (int jj = 0; jj < 4; jj++) {
        const int ic = ty * 4 + jj;
        const unsigned bits = __ballot_sync(0xffffffffu, tile[tx][ic] != 0);
        if (tx == 0) outb[(size_t)(bx + ic) * 128 + (by >> 5)] = bits;
    }
}

// ============================================================================
// merged double softmax with bit mask; fp16 in/out (in place), grid (NDIM, 3)
// ============================================================================
__device__ __forceinline__ float warp_red_max(float v) {
#pragma unroll
    for (int o = 16; o; o >>= 1) v = fmaxf(v, __shfl_xor_sync(0xffffffffu, v, o));
    return v;
}
__device__ __forceinline__ float warp_red_sum(float v) {
#pragma unroll
    for (int o = 16; o; o >>= 1) v += __shfl_xor_sync(0xffffffffu, v, o);
    return v;
}
template <bool IS_MAX>
__device__ __forceinline__ float block_red(float v, float* red, int t) {
    v = IS_MAX ? warp_red_max(v) : warp_red_sum(v);
    __syncthreads();
    if ((t & 31) == 0) red[t >> 5] = v;
    __syncthreads();
    if (t < 32) {
        float x = (t < 8) ? red[t] : (IS_MAX ? -INFINITY : 0.f);
        x = IS_MAX ? warp_red_max(x) : warp_red_sum(x);
        if (t == 0) red[0] = x;
    }
    __syncthreads();
    return red[0];
}

__global__ void __launch_bounds__(256) softmax2_kernel(
    __half* __restrict__ Sbase, const uint32_t* __restrict__ Mb)
{
    __shared__ float red[32];
    const int t = threadIdx.x;
    const size_t row = blockIdx.x;
    const int z = blockIdx.y;
    __half* Srow = Sbase + (size_t)z * NN + row * NDIM;
    const uint32_t* mb = Mb + (size_t)z * MBZ + row * 128;

    float r[16];
    float mx = -INFINITY;
#pragma unroll
    for (int c = 0; c < 2; c++) {
        uint4 raw = *(const uint4*)(Srow + c * 2048 + t * 8);
        const __half2* h2 = (const __half2*)&raw;
#pragma unroll
        for (int q = 0; q < 4; q++) {
            float2 f = __half22float2(h2[q]);
            r[c*8 + 2*q]     = f.x;
            r[c*8 + 2*q + 1] = f.y;
            mx = fmaxf(mx, fmaxf(f.x, f.y));
        }
    }
    const float smax = block_red<true>(mx, red, t);

    float sum = 0.f;
#pragma unroll
    for (int i = 0; i < 16; i++) { r[i] = __expf(r[i] - smax); sum += r[i]; }
    const float inv = 1.f / block_red<false>(sum, red, t);

    float mx2 = -INFINITY;
#pragma unroll
    for (int c = 0; c < 2; c++) {
        const uint32_t w = __ldg(&mb[c * 64 + (t >> 2)]);
        const uint32_t bits = (w >> ((t & 3) * 8)) & 0xFFu;
#pragma unroll
        for (int i = 0; i < 8; i++) {
            r[c*8 + i] = ((bits >> i) & 1u) ? (r[c*8 + i] * inv) : 0.f;
            mx2 = fmaxf(mx2, r[c*8 + i]);
        }
    }
    const float smax2 = block_red<true>(mx2, red, t);

    float sum2 = 0.f;
#pragma unroll
    for (int i = 0; i < 16; i++) { r[i] = __expf(r[i] - smax2); sum2 += r[i]; }
    const float inv2 = 1.f / block_red<false>(sum2, red, t);

#pragma unroll
    for (int c = 0; c < 2; c++) {
        uint4 raw;
        __half2* h2 = (__half2*)&raw;
#pragma unroll
        for (int q = 0; q < 4; q++) {
            h2[q].x = __float2half_rn(r[c*8 + 2*q]     * inv2);
            h2[q].y = __float2half_rn(r[c*8 + 2*q + 1] * inv2);
        }
        *(uint4*)(Srow + c * 2048 + t * 8) = raw;
    }
}

// ============================================================================
// launch (R16 topology; score GEMM z=0 exploits symmetry)
// ============================================================================
extern "C" void kernel_launch(void* const* d_in, const int* in_sizes, int n_in,
                              void* d_out, int out_size)
{
    const float* L      = (const float*)d_in[0];
    const float* H      = (const float*)d_in[1];
    const float* B_low  = (const float*)d_in[2];
    const float* H_low  = (const float*)d_in[3];
    const float* B_high = (const float*)d_in[4];
    const float* H_high = (const float*)d_in[5];
    const float* W      = (const float*)d_in[6];
    const float* bvec   = (const float*)d_in[7];
    float* out = (float*)d_out;

    __half *Sh, *Hh, *H4, *Wh;
    uint32_t* Mb;
    cudaGetSymbolAddress((void**)&Sh, g_Sh);
    cudaGetSymbolAddress((void**)&Hh, g_Hh);
    cudaGetSymbolAddress((void**)&H4, g_H4);
    cudaGetSymbolAddress((void**)&Wh, g_Wh);
    cudaGetSymbolAddress((void**)&Mb, g_Mb);

    const float scale = 0.03125f;  // 1/sqrt(1024)
    const int rt = 256;

    // [0] merged fp16 rounds of H tensors
    roundH_kernel<<<dim3((unsigned)(HSZ / 4 / rt), 3), rt>>>(H, H_low, H_high, Hh, (int)HSZ);
    // [1] bit masks for L and B_high (row-major)
    bitpack_rows_kernel<<<dim3(NDIM / 8, 2), 256>>>(L, B_high, Mb);
    // [2] transposed bit mask for B_low
    bitpack_T_kernel<<<dim3(NDIM / 32, NDIM / 32), dim3(32, 8)>>>(B_low, Mb + MBZ);

    // [3] merged score GEMM, f16 accumulators, 3 CTAs/SM (NT); z=0 symmetric
    gemm_tcore<true, false><<<dim3(NDIM / 128, NDIM / 128, 3), 256>>>(
        Hh, 0, DDIM, Hh, HSZ, DDIM,
        DDIM, 0, scale, Sh, nullptr, NN, NDIM, nullptr, 1);

    // [4] merged double softmax (in place, fp16, bit masks)
    softmax2_kernel<<<dim3(NDIM, 3), 256>>>(Sh, Mb);

    // [5] merged AV GEMM, f32 accumulators, NN path: B = Hh [token][feature]
    gemm_tcore<false, true><<<dim3(DDIM / 128, NDIM / 128, 3), 256>>>(
        Sh, NN, NDIM, Hh, HSZ, DDIM,
        NDIM, 0, 1.0f, H4, nullptr, DDIM, 3 * DDIM, nullptr, 0);

    // [6] W fp16 round
    round_kernel<<<(int)((size_t)DDIM * 3 * DDIM / 4 / rt), rt>>>(
        W, Wh, (int)((size_t)DDIM * 3 * DDIM));

    // [7] output GEMM: out = tanh(H4 @ W^T + b)  (NT)
    gemm_tcore<false, false><<<dim3(DDIM / 128, NDIM / 128, 1), 256>>>(
        H4, 0, 3 * DDIM, Wh, 0, 3 * DDIM,
        3 * DDIM, 1, 1.0f, nullptr, out, 0, DDIM, bvec, 0);
}